// round 7
// baseline (speedup 1.0000x reference)
#include <cuda_runtime.h>
#include <cuda_fp16.h>
#include <math.h>
#include <stdint.h>

#define HIDDEN 2048
#define NH 32
#define NKV 8
#define HD 64
#define BB 2
#define SEQ 2048
#define BSTOK (BB*SEQ)
#define QKVS 3072          // fused QKV row stride (halfs)
#define KOFF 2048          // K offset within QKV row
#define VOFF 2560          // V offset

// ---------------------------------------------------------------------------
// Scratch
// ---------------------------------------------------------------------------
__device__ __half g_xh  [(size_t)BSTOK * HIDDEN];
__device__ __half g_QKVh[(size_t)BSTOK * QKVS];
__device__ __half g_Oh  [(size_t)BSTOK * HIDDEN];
__device__ __half g_Wqkv[(size_t)QKVS * HIDDEN];   // [3072][2048] = WtQ|WtK|WtV
__device__ __half g_WtO [(size_t)HIDDEN * HIDDEN];
__device__ float  g_cos[BSTOK * 32];
__device__ float  g_sin[BSTOK * 32];

// ---------------------------------------------------------------------------
// Helpers
// ---------------------------------------------------------------------------
__device__ __forceinline__ uint32_t smem_u32(const void* p) {
    uint32_t a;
    asm("{ .reg .u64 t; cvta.to.shared.u64 t, %1; cvt.u32.u64 %0, t; }"
        : "=r"(a) : "l"(p));
    return a;
}
__device__ __forceinline__ void cp16(uint32_t dst, const void* src) {
    asm volatile("cp.async.cg.shared.global [%0], [%1], 16;"
                 :: "r"(dst), "l"(src));
}
__device__ __forceinline__ void cp_commit() {
    asm volatile("cp.async.commit_group;");
}
__device__ __forceinline__ void ldsm4(uint32_t* r, uint32_t addr) {
    asm volatile("ldmatrix.sync.aligned.m8n8.x4.shared.b16 {%0,%1,%2,%3}, [%4];"
                 : "=r"(r[0]), "=r"(r[1]), "=r"(r[2]), "=r"(r[3]) : "r"(addr));
}
__device__ __forceinline__ void ldsm4t(uint32_t* r, uint32_t addr) {
    asm volatile("ldmatrix.sync.aligned.m8n8.x4.trans.shared.b16 {%0,%1,%2,%3}, [%4];"
                 : "=r"(r[0]), "=r"(r[1]), "=r"(r[2]), "=r"(r[3]) : "r"(addr));
}
__device__ __forceinline__ void mma16(float* c, const uint32_t* a,
                                      uint32_t b0, uint32_t b1) {
    asm volatile(
        "mma.sync.aligned.m16n8k16.row.col.f32.f16.f16.f32 "
        "{%0,%1,%2,%3}, {%4,%5,%6,%7}, {%8,%9}, {%0,%1,%2,%3};"
        : "+f"(c[0]), "+f"(c[1]), "+f"(c[2]), "+f"(c[3])
        : "r"(a[0]), "r"(a[1]), "r"(a[2]), "r"(a[3]), "r"(b0), "r"(b1));
}

// ---------------------------------------------------------------------------
// fp16 mma GEMM with cp.async 3-stage pipeline.
// C[M,N] = A[M,K] @ Bt[N,K]^T.  CTA 128x128, 256 thr, warp 64x32, chunk 32.
// ---------------------------------------------------------------------------
#define KST2 40
#define CHUNKB (128 * KST2 * 2)       // 10240 B per tile-chunk
#define STAGEB (2 * CHUNKB)           // 20480
#define GEMM_SMEM_BYTES (3 * STAGEB)  // 61440

template<bool HOUT>
__global__ __launch_bounds__(256, 1) void gemm_h(
    const __half* __restrict__ A, const __half* __restrict__ Bt,
    void* __restrict__ Cv, int M, int N, int K) {
    extern __shared__ __half sh[];
    const uint32_t sbase = smem_u32(sh);
    const int tid  = threadIdx.x;
    const int wid  = tid >> 5;
    const int lane = tid & 31;
    const int gid  = lane >> 2;
    const int tid4 = lane & 3;
    const int wm   = wid & 1;
    const int wn   = wid >> 1;
    const int m0 = blockIdx.y * 128;
    const int n0 = blockIdx.x * 128;

    const int arow = (lane & 7) + ((lane >> 3) & 1) * 8;
    const int akof = (lane >> 4) * 8;
    const int brow = (lane & 7) + (lane >> 4) * 8;
    const int bkof = ((lane >> 3) & 1) * 8;

    int lrow[2], lv[2];
    #pragma unroll
    for (int i = 0; i < 2; i++) {
        int lin = i * 256 + tid;
        lrow[i] = lin >> 2;
        lv[i]   = lin & 3;
    }

    const __half* Ag = A  + (size_t)m0 * K;
    const __half* Bg = Bt + (size_t)n0 * K;
    const int nch = K / 32;

    float acc[4][4][4];
    #pragma unroll
    for (int mt = 0; mt < 4; mt++)
        #pragma unroll
        for (int nt = 0; nt < 4; nt++)
            #pragma unroll
            for (int c = 0; c < 4; c++) acc[mt][nt][c] = 0.f;

    // issue chunk ch into stage ch%3
    auto issue = [&](int ch) {
        uint32_t As = sbase + (ch % 3) * STAGEB;
        uint32_t Bs = As + CHUNKB;
        const __half* Agc = Ag + ch * 32;
        const __half* Bgc = Bg + ch * 32;
        #pragma unroll
        for (int i = 0; i < 2; i++) {
            uint32_t so = (uint32_t)(lrow[i] * KST2 + lv[i] * 8) * 2;
            cp16(As + so, Agc + (size_t)lrow[i] * K + lv[i] * 8);
            cp16(Bs + so, Bgc + (size_t)lrow[i] * K + lv[i] * 8);
        }
        cp_commit();
    };

    issue(0); issue(1); issue(2);

    for (int ch = 0; ch < nch; ch++) {
        asm volatile("cp.async.wait_group 2;");
        __syncthreads();

        const uint32_t As = sbase + (ch % 3) * STAGEB;
        const uint32_t Bs = As + CHUNKB;
        #pragma unroll
        for (int ks = 0; ks < 2; ks++) {
            uint32_t af[4][4], bf[4][2];
            #pragma unroll
            for (int mt = 0; mt < 4; mt++)
                ldsm4(af[mt], As + ((wm * 64 + mt * 16 + arow) * KST2
                                    + ks * 16 + akof) * 2);
            #pragma unroll
            for (int p = 0; p < 2; p++) {
                uint32_t b4[4];
                ldsm4(b4, Bs + ((wn * 32 + p * 16 + brow) * KST2
                                + ks * 16 + bkof) * 2);
                bf[2 * p][0] = b4[0]; bf[2 * p][1] = b4[1];
                bf[2 * p + 1][0] = b4[2]; bf[2 * p + 1][1] = b4[3];
            }
            #pragma unroll
            for (int mt = 0; mt < 4; mt++)
                #pragma unroll
                for (int nt = 0; nt < 4; nt++)
                    mma16(acc[mt][nt], af[mt], bf[nt][0], bf[nt][1]);
        }
        __syncthreads();

        if (ch + 3 < nch) issue(ch + 3);
        else cp_commit();          // empty group keeps wait_group arithmetic exact
    }

    #pragma unroll
    for (int mt = 0; mt < 4; mt++) {
        const int r = m0 + wm * 64 + mt * 16 + gid;
        #pragma unroll
        for (int nt = 0; nt < 4; nt++) {
            const int col = n0 + wn * 32 + nt * 8 + tid4 * 2;
            if (HOUT) {
                __half* C = (__half*)Cv;
                *(__half2*)(C + (size_t)r * N + col) =
                    __floats2half2_rn(acc[mt][nt][0], acc[mt][nt][1]);
                *(__half2*)(C + (size_t)(r + 8) * N + col) =
                    __floats2half2_rn(acc[mt][nt][2], acc[mt][nt][3]);
            } else {
                float* C = (float*)Cv;
                float2 v0 = { acc[mt][nt][0], acc[mt][nt][1] };
                float2 v1 = { acc[mt][nt][2], acc[mt][nt][3] };
                *(float2*)(C + (size_t)r * N + col)       = v0;
                *(float2*)(C + (size_t)(r + 8) * N + col) = v1;
            }
        }
    }
}

// ---------------------------------------------------------------------------
// fp32 -> fp16 convert
// ---------------------------------------------------------------------------
__global__ void convert_x(const float* __restrict__ X, __half* __restrict__ Xh,
                          int n4) {
    int idx = blockIdx.x * blockDim.x + threadIdx.x;
    if (idx >= n4) return;
    float4 v = ((const float4*)X)[idx];
    ((__half2*)Xh)[2 * idx]     = __floats2half2_rn(v.x, v.y);
    ((__half2*)Xh)[2 * idx + 1] = __floats2half2_rn(v.z, v.w);
}

// ---------------------------------------------------------------------------
// Weight transpose + convert: Wt[n][k] = (half)W[k][n]
// ---------------------------------------------------------------------------
__global__ void transpose_kh(const float* __restrict__ W, __half* __restrict__ Wt,
                             int R, int C) {
    __shared__ float tile[32][33];
    int c0 = blockIdx.x * 32, r0 = blockIdx.y * 32;
    int tx = threadIdx.x;
    for (int j = threadIdx.y; j < 32; j += 8)
        tile[j][tx] = W[(size_t)(r0 + j) * C + c0 + tx];
    __syncthreads();
    for (int j = threadIdx.y; j < 32; j += 8)
        Wt[(size_t)(c0 + j) * R + r0 + tx] = __float2half_rn(tile[tx][j]);
}

// ---------------------------------------------------------------------------
// RoPE table + in-place half apply (strided QKV layout)
// ---------------------------------------------------------------------------
__global__ void rope_table(const int* __restrict__ pos) {
    int idx = blockIdx.x * blockDim.x + threadIdx.x;
    if (idx >= BSTOK * 32) return;
    int i = idx & 31, bs = idx >> 5;
    double inv_freq = exp(-(double)i * (9.210340371976184 / 32.0));
    double a = (double)pos[bs] * inv_freq;
    double s, c;
    sincos(a, &s, &c);
    g_cos[idx] = (float)c;
    g_sin[idx] = (float)s;
}

__global__ void rope_apply_h2(__half* __restrict__ X, int nheads, int off) {
    int idx = blockIdx.x * blockDim.x + threadIdx.x;
    int total = BSTOK * nheads * 32;
    if (idx >= total) return;
    int i  = idx & 31;
    int h  = (idx >> 5) % nheads;
    int bs = idx / (nheads * 32);
    float c  = g_cos[bs * 32 + i];
    float sn = g_sin[bs * 32 + i];
    __half* p = X + (size_t)bs * QKVS + off + h * HD;
    float x1 = __half2float(p[i]), x2 = __half2float(p[i + 32]);
    p[i]      = __float2half_rn(x1 * c - x2 * sn);
    p[i + 32] = __float2half_rn(x2 * c + x1 * sn);
}

// ---------------------------------------------------------------------------
// fp16 flash attention: 128-query CTA (8 warps x 16 rows), 64-key tiles,
// cp.async double-buffered K/V, GQA 4:1, causal.
// ---------------------------------------------------------------------------
#define KSTH 72
#define KVT (64 * KSTH)                          // halfs per K (or V) tile
#define FLASH_SMEM ((4 * KVT + 128 * KSTH) * 2)  // 55296 B

__global__ __launch_bounds__(256, 1) void flash_h(
    const __half* __restrict__ QKV, __half* __restrict__ Oh) {
    extern __shared__ __half fsh[];
    const uint32_t fbase = smem_u32(fsh);
    __half* Ss = fsh + 4 * KVT;                  // [128][72]
    const uint32_t ssb = fbase + 4 * KVT * 2;

    const int tid  = threadIdx.x;
    const int warp = tid >> 5;
    const int lane = tid & 31;
    const int gid  = lane >> 2;
    const int tid4 = lane & 3;
    const int qb = blockIdx.x, h = blockIdx.y, b = blockIdx.z;
    const int hkv = h >> 2;
    const int row0 = warp * 16;

    const int arow = (lane & 7) + ((lane >> 3) & 1) * 8;
    const int akof = (lane >> 4) * 8;
    const int brow = (lane & 7) + (lane >> 4) * 8;
    const int bkof = ((lane >> 3) & 1) * 8;
    const int vrow = (lane & 7) + ((lane >> 3) & 1) * 8;
    const int vkof = (lane >> 4) * 8;

    // K/V tile issue into stage kt&1
    int klin[2], kv_[2];
    #pragma unroll
    for (int i = 0; i < 2; i++) {
        int lin = i * 256 + tid;
        klin[i] = lin >> 3;       // key row 0..63
        kv_[i]  = lin & 7;        // 16B chunk 0..7
    }
    auto issue = [&](int kt) {
        uint32_t Kb = fbase + (kt & 1) * 2 * KVT * 2;
        uint32_t Vb = Kb + KVT * 2;
        #pragma unroll
        for (int i = 0; i < 2; i++) {
            size_t rowb = (size_t)(b * SEQ + kt * 64 + klin[i]) * QKVS
                          + hkv * HD + kv_[i] * 8;
            uint32_t so = (uint32_t)(klin[i] * KSTH + kv_[i] * 8) * 2;
            cp16(Kb + so, QKV + rowb + KOFF);
            cp16(Vb + so, QKV + rowb + VOFF);
        }
        cp_commit();
    };

    // Stage this warp's 16 Q rows into Ss, grab fragments.
    #pragma unroll
    for (int j = 0; j < 4; j++) {
        int idx = j * 32 + lane;
        int r = idx >> 3, v = idx & 7;
        int token = b * SEQ + qb * 128 + row0 + r;
        *(uint4*)(Ss + (row0 + r) * KSTH + v * 8) =
            *(const uint4*)(QKV + (size_t)token * QKVS + h * HD + v * 8);
    }
    __syncwarp();
    uint32_t qf[4][4];
    #pragma unroll
    for (int ks = 0; ks < 4; ks++)
        ldsm4(qf[ks], ssb + ((row0 + arow) * KSTH + ks * 16 + akof) * 2);
    __syncwarp();

    float o[8][4];
    #pragma unroll
    for (int nt = 0; nt < 8; nt++)
        #pragma unroll
        for (int i = 0; i < 4; i++) o[nt][i] = 0.f;
    float m0 = -1e30f, m1 = -1e30f, l0 = 0.f, l1 = 0.f;

    const int ktmax = 2 * qb + 1;
    issue(0);

    for (int kt = 0; kt <= ktmax; kt++) {
        if (kt < ktmax) { issue(kt + 1); asm volatile("cp.async.wait_group 1;"); }
        else            {                asm volatile("cp.async.wait_group 0;"); }
        __syncthreads();

        const uint32_t ksb = fbase + (kt & 1) * 2 * KVT * 2;
        const uint32_t vsb = ksb + KVT * 2;
        const int k0 = kt * 64;

        // S = Q K^T
        float c[8][4];
        #pragma unroll
        for (int nt = 0; nt < 8; nt++)
            #pragma unroll
            for (int i = 0; i < 4; i++) c[nt][i] = 0.f;
        #pragma unroll
        for (int ks = 0; ks < 4; ks++)
            #pragma unroll
            for (int p = 0; p < 4; p++) {
                uint32_t b4[4];
                ldsm4(b4, ksb + ((p * 16 + brow) * KSTH + ks * 16 + bkof) * 2);
                mma16(c[2 * p],     qf[ks], b4[0], b4[1]);
                mma16(c[2 * p + 1], qf[ks], b4[2], b4[3]);
            }

        #pragma unroll
        for (int nt = 0; nt < 8; nt++)
            #pragma unroll
            for (int i = 0; i < 4; i++) c[nt][i] *= 0.125f;

        const int r0g = qb * 128 + row0 + gid;
        if (k0 + 63 > r0g) {   // any masking possible for this thread's rows
            #pragma unroll
            for (int nt = 0; nt < 8; nt++) {
                int cb = k0 + nt * 8 + 2 * tid4;
                if (cb     > r0g)     c[nt][0] = -1e30f;
                if (cb + 1 > r0g)     c[nt][1] = -1e30f;
                if (cb     > r0g + 8) c[nt][2] = -1e30f;
                if (cb + 1 > r0g + 8) c[nt][3] = -1e30f;
            }
        }

        // online softmax
        float t0 = -1e30f, t1 = -1e30f;
        #pragma unroll
        for (int nt = 0; nt < 8; nt++) {
            t0 = fmaxf(t0, fmaxf(c[nt][0], c[nt][1]));
            t1 = fmaxf(t1, fmaxf(c[nt][2], c[nt][3]));
        }
        t0 = fmaxf(t0, __shfl_xor_sync(0xffffffffu, t0, 1));
        t0 = fmaxf(t0, __shfl_xor_sync(0xffffffffu, t0, 2));
        t1 = fmaxf(t1, __shfl_xor_sync(0xffffffffu, t1, 1));
        t1 = fmaxf(t1, __shfl_xor_sync(0xffffffffu, t1, 2));
        float m0n = fmaxf(m0, t0);
        float m1n = fmaxf(m1, t1);
        float cor0 = __expf(m0 - m0n);
        float cor1 = __expf(m1 - m1n);
        #pragma unroll
        for (int nt = 0; nt < 8; nt++) {
            o[nt][0] *= cor0; o[nt][1] *= cor0;
            o[nt][2] *= cor1; o[nt][3] *= cor1;
        }

        float s0 = 0.f, s1 = 0.f;
        #pragma unroll
        for (int nt = 0; nt < 8; nt++) {
            float p0 = __expf(c[nt][0] - m0n);
            float p1 = __expf(c[nt][1] - m0n);
            float p2 = __expf(c[nt][2] - m1n);
            float p3 = __expf(c[nt][3] - m1n);
            s0 += p0 + p1;
            s1 += p2 + p3;
            *(__half2*)(Ss + (row0 + gid)     * KSTH + nt * 8 + 2 * tid4) =
                __floats2half2_rn(p0, p1);
            *(__half2*)(Ss + (row0 + gid + 8) * KSTH + nt * 8 + 2 * tid4) =
                __floats2half2_rn(p2, p3);
        }
        s0 += __shfl_xor_sync(0xffffffffu, s0, 1);
        s0 += __shfl_xor_sync(0xffffffffu, s0, 2);
        s1 += __shfl_xor_sync(0xffffffffu, s1, 1);
        s1 += __shfl_xor_sync(0xffffffffu, s1, 2);
        l0 = l0 * cor0 + s0;
        l1 = l1 * cor1 + s1;
        m0 = m0n; m1 = m1n;
        __syncwarp();

        // O += P V
        #pragma unroll
        for (int ks = 0; ks < 4; ks++) {
            uint32_t a4[4];
            ldsm4(a4, ssb + ((row0 + arow) * KSTH + ks * 16 + akof) * 2);
            #pragma unroll
            for (int p = 0; p < 4; p++) {
                uint32_t b4[4];
                ldsm4t(b4, vsb + ((ks * 16 + vrow) * KSTH + p * 16 + vkof) * 2);
                mma16(o[2 * p],     a4, b4[0], b4[1]);
                mma16(o[2 * p + 1], a4, b4[2], b4[3]);
            }
        }
        __syncthreads();
    }

    float inv0 = 1.f / l0, inv1 = 1.f / l1;
    int token0 = b * SEQ + qb * 128 + row0 + gid;
    __half* op0 = Oh + (size_t)token0 * HIDDEN + h * HD;
    __half* op1 = op0 + (size_t)8 * HIDDEN;
    #pragma unroll
    for (int nt = 0; nt < 8; nt++) {
        int col = nt * 8 + 2 * tid4;
        *(__half2*)(op0 + col) = __floats2half2_rn(o[nt][0] * inv0, o[nt][1] * inv0);
        *(__half2*)(op1 + col) = __floats2half2_rn(o[nt][2] * inv1, o[nt][3] * inv1);
    }
}

// ---------------------------------------------------------------------------
// Launch sequence (fused QKV GEMM is launch index 5 -> ncu captures it)
// ---------------------------------------------------------------------------
extern "C" void kernel_launch(void* const* d_in, const int* in_sizes, int n_in,
                              void* d_out, int out_size) {
    const float* x   = (const float*)d_in[0];
    const float* Wq  = (const float*)d_in[1];
    const float* Wk  = (const float*)d_in[2];
    const float* Wv  = (const float*)d_in[3];
    const float* Wo  = (const float*)d_in[4];
    const int*   pos = (const int*)d_in[5];
    float* out = (float*)d_out;

    __half *xh, *QKVh, *Oh, *Wqkv, *WtO;
    cudaGetSymbolAddress((void**)&xh,   g_xh);
    cudaGetSymbolAddress((void**)&QKVh, g_QKVh);
    cudaGetSymbolAddress((void**)&Oh,   g_Oh);
    cudaGetSymbolAddress((void**)&Wqkv, g_Wqkv);
    cudaGetSymbolAddress((void**)&WtO,  g_WtO);

    cudaFuncSetAttribute(gemm_h<true>,  cudaFuncAttributeMaxDynamicSharedMemorySize, GEMM_SMEM_BYTES);
    cudaFuncSetAttribute(gemm_h<false>, cudaFuncAttributeMaxDynamicSharedMemorySize, GEMM_SMEM_BYTES);
    cudaFuncSetAttribute(flash_h,       cudaFuncAttributeMaxDynamicSharedMemorySize, FLASH_SMEM);

    const int M = BSTOK;        // 4096
    dim3 tb(32, 8);

    // 0: convert x
    convert_x<<<(BSTOK * HIDDEN / 4 + 255) / 256, 256>>>(x, xh, BSTOK * HIDDEN / 4);
    // 1-4: weight transposes (QKV concatenated)
    transpose_kh<<<dim3(HIDDEN / 32, HIDDEN / 32), tb>>>(Wq, Wqkv, HIDDEN, HIDDEN);
    transpose_kh<<<dim3((NKV * HD) / 32, HIDDEN / 32), tb>>>(
        Wk, Wqkv + (size_t)KOFF * HIDDEN, HIDDEN, NKV * HD);
    transpose_kh<<<dim3((NKV * HD) / 32, HIDDEN / 32), tb>>>(
        Wv, Wqkv + (size_t)VOFF * HIDDEN, HIDDEN, NKV * HD);
    transpose_kh<<<dim3(HIDDEN / 32, HIDDEN / 32), tb>>>(Wo, WtO, HIDDEN, HIDDEN);

    // 5: fused QKV projection (half out)
    gemm_h<true><<<dim3(QKVS / 128, M / 128), 256, GEMM_SMEM_BYTES>>>(
        xh, Wqkv, QKVh, M, QKVS, HIDDEN);

    // 6-8: RoPE
    rope_table<<<(BSTOK * 32 + 255) / 256, 256>>>(pos);
    rope_apply_h2<<<(BSTOK * NH * 32 + 255) / 256, 256>>>(QKVh, NH, 0);
    rope_apply_h2<<<(BSTOK * NKV * 32 + 255) / 256, 256>>>(QKVh, NKV, KOFF);

    // 9: flash attention (128-query CTAs)
    flash_h<<<dim3(SEQ / 128, NH, BB), 256, FLASH_SMEM>>>(QKVh, Oh);

    // 10: output projection (fp32 out)
    gemm_h<false><<<dim3(HIDDEN / 128, M / 128), 256, GEMM_SMEM_BYTES>>>(
        Oh, WtO, out, M, HIDDEN, HIDDEN);
}

// round 9
// speedup vs baseline: 1.0729x; 1.0729x over previous
#include <cuda_runtime.h>
#include <cuda_fp16.h>
#include <math.h>
#include <stdint.h>

#define HIDDEN 2048
#define NH 32
#define NKV 8
#define HD 64
#define BB 2
#define SEQ 2048
#define BSTOK (BB*SEQ)
#define QKVS 3072          // fused QKV row stride (halfs)
#define KOFF 2048
#define VOFF 2560

// ---------------------------------------------------------------------------
// Scratch
// ---------------------------------------------------------------------------
__device__ __half g_xh  [(size_t)BSTOK * HIDDEN];
__device__ __half g_QKVh[(size_t)BSTOK * QKVS];
__device__ __half g_Oh  [(size_t)BSTOK * HIDDEN];
__device__ __half g_Wqkv[(size_t)QKVS * HIDDEN];
__device__ __half g_WtO [(size_t)HIDDEN * HIDDEN];
__device__ float  g_cos[BSTOK * 32];
__device__ float  g_sin[BSTOK * 32];

// ---------------------------------------------------------------------------
// Helpers
// ---------------------------------------------------------------------------
__device__ __forceinline__ uint32_t smem_u32(const void* p) {
    uint32_t a;
    asm("{ .reg .u64 t; cvta.to.shared.u64 t, %1; cvt.u32.u64 %0, t; }"
        : "=r"(a) : "l"(p));
    return a;
}
__device__ __forceinline__ void cp16(uint32_t dst, const void* src) {
    asm volatile("cp.async.cg.shared.global [%0], [%1], 16;"
                 :: "r"(dst), "l"(src));
}
__device__ __forceinline__ void cp_commit() {
    asm volatile("cp.async.commit_group;");
}
__device__ __forceinline__ void ldsm4(uint32_t* r, uint32_t addr) {
    asm volatile("ldmatrix.sync.aligned.m8n8.x4.shared.b16 {%0,%1,%2,%3}, [%4];"
                 : "=r"(r[0]), "=r"(r[1]), "=r"(r[2]), "=r"(r[3]) : "r"(addr));
}
__device__ __forceinline__ void ldsm4t(uint32_t* r, uint32_t addr) {
    asm volatile("ldmatrix.sync.aligned.m8n8.x4.trans.shared.b16 {%0,%1,%2,%3}, [%4];"
                 : "=r"(r[0]), "=r"(r[1]), "=r"(r[2]), "=r"(r[3]) : "r"(addr));
}
__device__ __forceinline__ void mma16(float* c, const uint32_t* a,
                                      uint32_t b0, uint32_t b1) {
    asm volatile(
        "mma.sync.aligned.m16n8k16.row.col.f32.f16.f16.f32 "
        "{%0,%1,%2,%3}, {%4,%5,%6,%7}, {%8,%9}, {%0,%1,%2,%3};"
        : "+f"(c[0]), "+f"(c[1]), "+f"(c[2]), "+f"(c[3])
        : "r"(a[0]), "r"(a[1]), "r"(a[2]), "r"(a[3]), "r"(b0), "r"(b1));
}

// ---------------------------------------------------------------------------
// fp16 mma GEMM with cp.async 3-stage pipeline (unchanged from R6).
// ---------------------------------------------------------------------------
#define KST2 40
#define CHUNKB (128 * KST2 * 2)
#define STAGEB (2 * CHUNKB)
#define GEMM_SMEM_BYTES (3 * STAGEB)

template<bool HOUT>
__global__ __launch_bounds__(256, 1) void gemm_h(
    const __half* __restrict__ A, const __half* __restrict__ Bt,
    void* __restrict__ Cv, int M, int N, int K) {
    extern __shared__ __half sh[];
    const uint32_t sbase = smem_u32(sh);
    const int tid  = threadIdx.x;
    const int wid  = tid >> 5;
    const int lane = tid & 31;
    const int gid  = lane >> 2;
    const int tid4 = lane & 3;
    const int wm   = wid & 1;
    const int wn   = wid >> 1;
    const int m0 = blockIdx.y * 128;
    const int n0 = blockIdx.x * 128;

    const int arow = (lane & 7) + ((lane >> 3) & 1) * 8;
    const int akof = (lane >> 4) * 8;
    const int brow = (lane & 7) + (lane >> 4) * 8;
    const int bkof = ((lane >> 3) & 1) * 8;

    int lrow[2], lv[2];
    #pragma unroll
    for (int i = 0; i < 2; i++) {
        int lin = i * 256 + tid;
        lrow[i] = lin >> 2;
        lv[i]   = lin & 3;
    }

    const __half* Ag = A  + (size_t)m0 * K;
    const __half* Bg = Bt + (size_t)n0 * K;
    const int nch = K / 32;

    float acc[4][4][4];
    #pragma unroll
    for (int mt = 0; mt < 4; mt++)
        #pragma unroll
        for (int nt = 0; nt < 4; nt++)
            #pragma unroll
            for (int c = 0; c < 4; c++) acc[mt][nt][c] = 0.f;

    auto issue = [&](int ch) {
        uint32_t As = sbase + (ch % 3) * STAGEB;
        uint32_t Bs = As + CHUNKB;
        const __half* Agc = Ag + ch * 32;
        const __half* Bgc = Bg + ch * 32;
        #pragma unroll
        for (int i = 0; i < 2; i++) {
            uint32_t so = (uint32_t)(lrow[i] * KST2 + lv[i] * 8) * 2;
            cp16(As + so, Agc + (size_t)lrow[i] * K + lv[i] * 8);
            cp16(Bs + so, Bgc + (size_t)lrow[i] * K + lv[i] * 8);
        }
        cp_commit();
    };

    issue(0); issue(1); issue(2);

    for (int ch = 0; ch < nch; ch++) {
        asm volatile("cp.async.wait_group 2;");
        __syncthreads();

        const uint32_t As = sbase + (ch % 3) * STAGEB;
        const uint32_t Bs = As + CHUNKB;
        #pragma unroll
        for (int ks = 0; ks < 2; ks++) {
            uint32_t af[4][4], bf[4][2];
            #pragma unroll
            for (int mt = 0; mt < 4; mt++)
                ldsm4(af[mt], As + ((wm * 64 + mt * 16 + arow) * KST2
                                    + ks * 16 + akof) * 2);
            #pragma unroll
            for (int p = 0; p < 2; p++) {
                uint32_t b4[4];
                ldsm4(b4, Bs + ((wn * 32 + p * 16 + brow) * KST2
                                + ks * 16 + bkof) * 2);
                bf[2 * p][0] = b4[0]; bf[2 * p][1] = b4[1];
                bf[2 * p + 1][0] = b4[2]; bf[2 * p + 1][1] = b4[3];
            }
            #pragma unroll
            for (int mt = 0; mt < 4; mt++)
                #pragma unroll
                for (int nt = 0; nt < 4; nt++)
                    mma16(acc[mt][nt], af[mt], bf[nt][0], bf[nt][1]);
        }
        __syncthreads();

        if (ch + 3 < nch) issue(ch + 3);
        else cp_commit();
    }

    #pragma unroll
    for (int mt = 0; mt < 4; mt++) {
        const int r = m0 + wm * 64 + mt * 16 + gid;
        #pragma unroll
        for (int nt = 0; nt < 4; nt++) {
            const int col = n0 + wn * 32 + nt * 8 + tid4 * 2;
            if (HOUT) {
                __half* C = (__half*)Cv;
                *(__half2*)(C + (size_t)r * N + col) =
                    __floats2half2_rn(acc[mt][nt][0], acc[mt][nt][1]);
                *(__half2*)(C + (size_t)(r + 8) * N + col) =
                    __floats2half2_rn(acc[mt][nt][2], acc[mt][nt][3]);
            } else {
                float* C = (float*)Cv;
                float2 v0 = { acc[mt][nt][0], acc[mt][nt][1] };
                float2 v1 = { acc[mt][nt][2], acc[mt][nt][3] };
                *(float2*)(C + (size_t)r * N + col)       = v0;
                *(float2*)(C + (size_t)(r + 8) * N + col) = v1;
            }
        }
    }
}

// ---------------------------------------------------------------------------
// Small kernels
// ---------------------------------------------------------------------------
__global__ void convert_x(const float* __restrict__ X, __half* __restrict__ Xh,
                          int n4) {
    int idx = blockIdx.x * blockDim.x + threadIdx.x;
    if (idx >= n4) return;
    float4 v = ((const float4*)X)[idx];
    ((__half2*)Xh)[2 * idx]     = __floats2half2_rn(v.x, v.y);
    ((__half2*)Xh)[2 * idx + 1] = __floats2half2_rn(v.z, v.w);
}

__global__ void transpose_kh(const float* __restrict__ W, __half* __restrict__ Wt,
                             int R, int C) {
    __shared__ float tile[32][33];
    int c0 = blockIdx.x * 32, r0 = blockIdx.y * 32;
    int tx = threadIdx.x;
    for (int j = threadIdx.y; j < 32; j += 8)
        tile[j][tx] = W[(size_t)(r0 + j) * C + c0 + tx];
    __syncthreads();
    for (int j = threadIdx.y; j < 32; j += 8)
        Wt[(size_t)(c0 + j) * R + r0 + tx] = __float2half_rn(tile[tx][j]);
}

__global__ void rope_table(const int* __restrict__ pos) {
    int idx = blockIdx.x * blockDim.x + threadIdx.x;
    if (idx >= BSTOK * 32) return;
    int i = idx & 31, bs = idx >> 5;
    double inv_freq = exp(-(double)i * (9.210340371976184 / 32.0));
    double a = (double)pos[bs] * inv_freq;
    double s, c;
    sincos(a, &s, &c);
    g_cos[idx] = (float)c;
    g_sin[idx] = (float)s;
}

__global__ void rope_apply_h2(__half* __restrict__ X, int nheads, int off) {
    int idx = blockIdx.x * blockDim.x + threadIdx.x;
    int total = BSTOK * nheads * 32;
    if (idx >= total) return;
    int i  = idx & 31;
    int h  = (idx >> 5) % nheads;
    int bs = idx / (nheads * 32);
    float c  = g_cos[bs * 32 + i];
    float sn = g_sin[bs * 32 + i];
    __half* p = X + (size_t)bs * QKVS + off + h * HD;
    float x1 = __half2float(p[i]), x2 = __half2float(p[i + 32]);
    p[i]      = __float2half_rn(x1 * c - x2 * sn);
    p[i + 32] = __float2half_rn(x2 * c + x1 * sn);
}

// ---------------------------------------------------------------------------
// fp16 flash attention: 64-query CTA (4 warps x 16 rows) -> 3 CTAs/SM,
// cp.async double-buffered 64-key K/V tiles, GQA 4:1, causal.
// smem: K0 V0 K1 V1 Ss  = 5 * 64*72*2 = 46080 B
// ---------------------------------------------------------------------------
#define KSTH 72
#define KVT (64 * KSTH)
#define FLASH_SMEM (5 * KVT * 2)

__global__ __launch_bounds__(128, 1) void flash_h(
    const __half* __restrict__ QKV, __half* __restrict__ Oh) {
    extern __shared__ __half fsh[];
    const uint32_t fbase = smem_u32(fsh);
    __half* Ss = fsh + 4 * KVT;                  // [64][72]
    const uint32_t ssb = fbase + 4 * KVT * 2;

    const int tid  = threadIdx.x;
    const int warp = tid >> 5;
    const int lane = tid & 31;
    const int gid  = lane >> 2;
    const int tid4 = lane & 3;
    const int qb = blockIdx.x, h = blockIdx.y, b = blockIdx.z;
    const int hkv = h >> 2;
    const int row0 = warp * 16;

    const int arow = (lane & 7) + ((lane >> 3) & 1) * 8;
    const int akof = (lane >> 4) * 8;
    const int brow = (lane & 7) + (lane >> 4) * 8;
    const int bkof = ((lane >> 3) & 1) * 8;
    const int vrow = (lane & 7) + ((lane >> 3) & 1) * 8;
    const int vkof = (lane >> 4) * 8;

    // K/V issue: 512 cp16 per tile per matrix / 128 threads = 4 each
    int klin[4], kv_[4];
    #pragma unroll
    for (int i = 0; i < 4; i++) {
        int lin = i * 128 + tid;
        klin[i] = lin >> 3;       // key 0..63
        kv_[i]  = lin & 7;        // 16B chunk
    }
    auto issue = [&](int kt) {
        uint32_t Kb = fbase + (kt & 1) * 2 * KVT * 2;
        uint32_t Vb = Kb + KVT * 2;
        #pragma unroll
        for (int i = 0; i < 4; i++) {
            size_t rowb = (size_t)(b * SEQ + kt * 64 + klin[i]) * QKVS
                          + hkv * HD + kv_[i] * 8;
            uint32_t so = (uint32_t)(klin[i] * KSTH + kv_[i] * 8) * 2;
            cp16(Kb + so, QKV + rowb + KOFF);
            cp16(Vb + so, QKV + rowb + VOFF);
        }
        cp_commit();
    };

    // Stage Q stripe into Ss, cache fragments.
    #pragma unroll
    for (int j = 0; j < 4; j++) {
        int idx = j * 32 + lane;
        int r = idx >> 3, v = idx & 7;
        int token = b * SEQ + qb * 64 + row0 + r;
        *(uint4*)(Ss + (row0 + r) * KSTH + v * 8) =
            *(const uint4*)(QKV + (size_t)token * QKVS + h * HD + v * 8);
    }
    __syncwarp();
    uint32_t qf[4][4];
    #pragma unroll
    for (int ks = 0; ks < 4; ks++)
        ldsm4(qf[ks], ssb + ((row0 + arow) * KSTH + ks * 16 + akof) * 2);
    __syncwarp();

    float o[8][4];
    #pragma unroll
    for (int nt = 0; nt < 8; nt++)
        #pragma unroll
        for (int i = 0; i < 4; i++) o[nt][i] = 0.f;
    float m0 = -1e30f, m1 = -1e30f, l0 = 0.f, l1 = 0.f;

    issue(0);

    for (int kt = 0; kt <= qb; kt++) {
        if (kt < qb) { issue(kt + 1); asm volatile("cp.async.wait_group 1;"); }
        else         {                asm volatile("cp.async.wait_group 0;"); }
        __syncthreads();

        const uint32_t ksb = fbase + (kt & 1) * 2 * KVT * 2;
        const uint32_t vsb = ksb + KVT * 2;

        // S = Q K^T
        float c[8][4];
        #pragma unroll
        for (int nt = 0; nt < 8; nt++)
            #pragma unroll
            for (int i = 0; i < 4; i++) c[nt][i] = 0.f;
        #pragma unroll
        for (int ks = 0; ks < 4; ks++)
            #pragma unroll
            for (int p = 0; p < 4; p++) {
                uint32_t b4[4];
                ldsm4(b4, ksb + ((p * 16 + brow) * KSTH + ks * 16 + bkof) * 2);
                mma16(c[2 * p],     qf[ks], b4[0], b4[1]);
                mma16(c[2 * p + 1], qf[ks], b4[2], b4[3]);
            }

        #pragma unroll
        for (int nt = 0; nt < 8; nt++)
            #pragma unroll
            for (int i = 0; i < 4; i++) c[nt][i] *= 0.125f;
        if (kt == qb) {
            const int r0l = row0 + gid, r1l = row0 + gid + 8;
            #pragma unroll
            for (int nt = 0; nt < 8; nt++) {
                int cb = nt * 8 + 2 * tid4;
                if (cb     > r0l) c[nt][0] = -1e30f;
                if (cb + 1 > r0l) c[nt][1] = -1e30f;
                if (cb     > r1l) c[nt][2] = -1e30f;
                if (cb + 1 > r1l) c[nt][3] = -1e30f;
            }
        }

        // online softmax
        float t0 = -1e30f, t1 = -1e30f;
        #pragma unroll
        for (int nt = 0; nt < 8; nt++) {
            t0 = fmaxf(t0, fmaxf(c[nt][0], c[nt][1]));
            t1 = fmaxf(t1, fmaxf(c[nt][2], c[nt][3]));
        }
        t0 = fmaxf(t0, __shfl_xor_sync(0xffffffffu, t0, 1));
        t0 = fmaxf(t0, __shfl_xor_sync(0xffffffffu, t0, 2));
        t1 = fmaxf(t1, __shfl_xor_sync(0xffffffffu, t1, 1));
        t1 = fmaxf(t1, __shfl_xor_sync(0xffffffffu, t1, 2));
        float m0n = fmaxf(m0, t0);
        float m1n = fmaxf(m1, t1);
        float cor0 = __expf(m0 - m0n);
        float cor1 = __expf(m1 - m1n);
        #pragma unroll
        for (int nt = 0; nt < 8; nt++) {
            o[nt][0] *= cor0; o[nt][1] *= cor0;
            o[nt][2] *= cor1; o[nt][3] *= cor1;
        }

        float s0 = 0.f, s1 = 0.f;
        #pragma unroll
        for (int nt = 0; nt < 8; nt++) {
            float p0 = __expf(c[nt][0] - m0n);
            float p1 = __expf(c[nt][1] - m0n);
            float p2 = __expf(c[nt][2] - m1n);
            float p3 = __expf(c[nt][3] - m1n);
            s0 += p0 + p1;
            s1 += p2 + p3;
            *(__half2*)(Ss + (row0 + gid)     * KSTH + nt * 8 + 2 * tid4) =
                __floats2half2_rn(p0, p1);
            *(__half2*)(Ss + (row0 + gid + 8) * KSTH + nt * 8 + 2 * tid4) =
                __floats2half2_rn(p2, p3);
        }
        s0 += __shfl_xor_sync(0xffffffffu, s0, 1);
        s0 += __shfl_xor_sync(0xffffffffu, s0, 2);
        s1 += __shfl_xor_sync(0xffffffffu, s1, 1);
        s1 += __shfl_xor_sync(0xffffffffu, s1, 2);
        l0 = l0 * cor0 + s0;
        l1 = l1 * cor1 + s1;
        m0 = m0n; m1 = m1n;
        __syncwarp();

        // O += P V
        #pragma unroll
        for (int ks = 0; ks < 4; ks++) {
            uint32_t a4[4];
            ldsm4(a4, ssb + ((row0 + arow) * KSTH + ks * 16 + akof) * 2);
            #pragma unroll
            for (int p = 0; p < 4; p++) {
                uint32_t b4[4];
                ldsm4t(b4, vsb + ((ks * 16 + vrow) * KSTH + p * 16 + vkof) * 2);
                mma16(o[2 * p],     a4, b4[0], b4[1]);
                mma16(o[2 * p + 1], a4, b4[2], b4[3]);
            }
        }
        __syncthreads();
    }

    float inv0 = 1.f / l0, inv1 = 1.f / l1;
    int token0 = b * SEQ + qb * 64 + row0 + gid;
    __half* op0 = Oh + (size_t)token0 * HIDDEN + h * HD;
    __half* op1 = op0 + (size_t)8 * HIDDEN;
    #pragma unroll
    for (int nt = 0; nt < 8; nt++) {
        int col = nt * 8 + 2 * tid4;
        *(__half2*)(op0 + col) = __floats2half2_rn(o[nt][0] * inv0, o[nt][1] * inv0);
        *(__half2*)(op1 + col) = __floats2half2_rn(o[nt][2] * inv1, o[nt][3] * inv1);
    }
}

// ---------------------------------------------------------------------------
// Launch sequence
// ---------------------------------------------------------------------------
extern "C" void kernel_launch(void* const* d_in, const int* in_sizes, int n_in,
                              void* d_out, int out_size) {
    const float* x   = (const float*)d_in[0];
    const float* Wq  = (const float*)d_in[1];
    const float* Wk  = (const float*)d_in[2];
    const float* Wv  = (const float*)d_in[3];
    const float* Wo  = (const float*)d_in[4];
    const int*   pos = (const int*)d_in[5];
    float* out = (float*)d_out;

    __half *xh, *QKVh, *Oh, *Wqkv, *WtO;
    cudaGetSymbolAddress((void**)&xh,   g_xh);
    cudaGetSymbolAddress((void**)&QKVh, g_QKVh);
    cudaGetSymbolAddress((void**)&Oh,   g_Oh);
    cudaGetSymbolAddress((void**)&Wqkv, g_Wqkv);
    cudaGetSymbolAddress((void**)&WtO,  g_WtO);

    cudaFuncSetAttribute(gemm_h<true>,  cudaFuncAttributeMaxDynamicSharedMemorySize, GEMM_SMEM_BYTES);
    cudaFuncSetAttribute(gemm_h<false>, cudaFuncAttributeMaxDynamicSharedMemorySize, GEMM_SMEM_BYTES);
    cudaFuncSetAttribute(flash_h,       cudaFuncAttributeMaxDynamicSharedMemorySize, FLASH_SMEM);

    const int M = BSTOK;        // 4096
    dim3 tb(32, 8);

    convert_x<<<(BSTOK * HIDDEN / 4 + 255) / 256, 256>>>(x, xh, BSTOK * HIDDEN / 4);
    transpose_kh<<<dim3(HIDDEN / 32, HIDDEN / 32), tb>>>(Wq, Wqkv, HIDDEN, HIDDEN);
    transpose_kh<<<dim3((NKV * HD) / 32, HIDDEN / 32), tb>>>(
        Wk, Wqkv + (size_t)KOFF * HIDDEN, HIDDEN, NKV * HD);
    transpose_kh<<<dim3((NKV * HD) / 32, HIDDEN / 32), tb>>>(
        Wv, Wqkv + (size_t)VOFF * HIDDEN, HIDDEN, NKV * HD);
    transpose_kh<<<dim3(HIDDEN / 32, HIDDEN / 32), tb>>>(Wo, WtO, HIDDEN, HIDDEN);

    // fused QKV projection
    gemm_h<true><<<dim3(QKVS / 128, M / 128), 256, GEMM_SMEM_BYTES>>>(
        xh, Wqkv, QKVh, M, QKVS, HIDDEN);

    rope_table<<<(BSTOK * 32 + 255) / 256, 256>>>(pos);
    rope_apply_h2<<<(BSTOK * NH * 32 + 255) / 256, 256>>>(QKVh, NH, 0);
    rope_apply_h2<<<(BSTOK * NKV * 32 + 255) / 256, 256>>>(QKVh, NKV, KOFF);

    // flash attention (64-query CTAs, cp.async K/V)
    flash_h<<<dim3(SEQ / 64, NH, BB), 128, FLASH_SMEM>>>(QKVh, Oh);

    // output projection
    gemm_h<false><<<dim3(HIDDEN / 128, M / 128), 256, GEMM_SMEM_BYTES>>>(
        Oh, WtO, out, M, HIDDEN, HIDDEN);
}

// round 10
// speedup vs baseline: 1.2125x; 1.1302x over previous
#include <cuda_runtime.h>
#include <cuda_fp16.h>
#include <math.h>
#include <stdint.h>

#define HIDDEN 2048
#define NH 32
#define NKV 8
#define HD 64
#define BB 2
#define SEQ 2048
#define BSTOK (BB*SEQ)
#define QKVS 3072          // fused QKV row stride (halfs)
#define KOFF 2048
#define VOFF 2560

// ---------------------------------------------------------------------------
// Scratch
// ---------------------------------------------------------------------------
__device__ __half g_xh  [(size_t)BSTOK * HIDDEN];
__device__ __half g_QKVh[(size_t)BSTOK * QKVS];
__device__ __half g_Oh  [(size_t)BSTOK * HIDDEN];
__device__ __half g_Wqkv[(size_t)QKVS * HIDDEN];
__device__ __half g_WtO [(size_t)HIDDEN * HIDDEN];
__device__ float  g_cos[BSTOK * 32];
__device__ float  g_sin[BSTOK * 32];

// ---------------------------------------------------------------------------
// Helpers
// ---------------------------------------------------------------------------
__device__ __forceinline__ uint32_t smem_u32(const void* p) {
    uint32_t a;
    asm("{ .reg .u64 t; cvta.to.shared.u64 t, %1; cvt.u32.u64 %0, t; }"
        : "=r"(a) : "l"(p));
    return a;
}
__device__ __forceinline__ void cp16(uint32_t dst, const void* src) {
    asm volatile("cp.async.cg.shared.global [%0], [%1], 16;"
                 :: "r"(dst), "l"(src));
}
__device__ __forceinline__ void cp_commit() {
    asm volatile("cp.async.commit_group;");
}
__device__ __forceinline__ void ldsm4(uint32_t* r, uint32_t addr) {
    asm volatile("ldmatrix.sync.aligned.m8n8.x4.shared.b16 {%0,%1,%2,%3}, [%4];"
                 : "=r"(r[0]), "=r"(r[1]), "=r"(r[2]), "=r"(r[3]) : "r"(addr));
}
__device__ __forceinline__ void ldsm4t(uint32_t* r, uint32_t addr) {
    asm volatile("ldmatrix.sync.aligned.m8n8.x4.trans.shared.b16 {%0,%1,%2,%3}, [%4];"
                 : "=r"(r[0]), "=r"(r[1]), "=r"(r[2]), "=r"(r[3]) : "r"(addr));
}
__device__ __forceinline__ void mma16(float* c, const uint32_t* a,
                                      uint32_t b0, uint32_t b1) {
    asm volatile(
        "mma.sync.aligned.m16n8k16.row.col.f32.f16.f16.f32 "
        "{%0,%1,%2,%3}, {%4,%5,%6,%7}, {%8,%9}, {%0,%1,%2,%3};"
        : "+f"(c[0]), "+f"(c[1]), "+f"(c[2]), "+f"(c[3])
        : "r"(a[0]), "r"(a[1]), "r"(a[2]), "r"(a[3]), "r"(b0), "r"(b1));
}

// ---------------------------------------------------------------------------
// fp16 mma GEMM, cp.async 3-stage pipeline, K-chunk 64 (4 k16 steps/sync).
// C[M,N] = A[M,K] @ Bt[N,K]^T.  CTA 128x128, 256 thr, warp 64x32.
// Smem row stride 72 halfs (144B == 4 banks mod 32 -> ldmatrix conflict-free).
// ---------------------------------------------------------------------------
#define KSTG 72
#define CHUNKB (128 * KSTG * 2)       // 18432 B per matrix per chunk
#define STAGEB (2 * CHUNKB)           // 36864
#define GEMM_SMEM_BYTES (3 * STAGEB)  // 110592

template<bool HOUT>
__global__ __launch_bounds__(256, 1) void gemm_h(
    const __half* __restrict__ A, const __half* __restrict__ Bt,
    void* __restrict__ Cv, int M, int N, int K) {
    extern __shared__ __half sh[];
    const uint32_t sbase = smem_u32(sh);
    const int tid  = threadIdx.x;
    const int wid  = tid >> 5;
    const int lane = tid & 31;
    const int gid  = lane >> 2;
    const int tid4 = lane & 3;
    const int wm   = wid & 1;
    const int wn   = wid >> 1;
    const int m0 = blockIdx.y * 128;
    const int n0 = blockIdx.x * 128;

    const int arow = (lane & 7) + ((lane >> 3) & 1) * 8;
    const int akof = (lane >> 4) * 8;
    const int brow = (lane & 7) + (lane >> 4) * 8;
    const int bkof = ((lane >> 3) & 1) * 8;

    // cooperative load: 128 rows x 64 halfs = 1024 cp16 per matrix, 4/thread
    int lrow[4], lv[4];
    #pragma unroll
    for (int i = 0; i < 4; i++) {
        int lin = i * 256 + tid;
        lrow[i] = lin >> 3;
        lv[i]   = lin & 7;
    }

    const __half* Ag = A  + (size_t)m0 * K;
    const __half* Bg = Bt + (size_t)n0 * K;
    const int nch = K / 64;

    float acc[4][4][4];
    #pragma unroll
    for (int mt = 0; mt < 4; mt++)
        #pragma unroll
        for (int nt = 0; nt < 4; nt++)
            #pragma unroll
            for (int c = 0; c < 4; c++) acc[mt][nt][c] = 0.f;

    auto issue = [&](int ch) {
        uint32_t As = sbase + (ch % 3) * STAGEB;
        uint32_t Bs = As + CHUNKB;
        const __half* Agc = Ag + ch * 64;
        const __half* Bgc = Bg + ch * 64;
        #pragma unroll
        for (int i = 0; i < 4; i++) {
            uint32_t so = (uint32_t)(lrow[i] * KSTG + lv[i] * 8) * 2;
            cp16(As + so, Agc + (size_t)lrow[i] * K + lv[i] * 8);
            cp16(Bs + so, Bgc + (size_t)lrow[i] * K + lv[i] * 8);
        }
        cp_commit();
    };

    issue(0); issue(1); issue(2);

    for (int ch = 0; ch < nch; ch++) {
        asm volatile("cp.async.wait_group 2;");
        __syncthreads();

        const uint32_t As = sbase + (ch % 3) * STAGEB;
        const uint32_t Bs = As + CHUNKB;
        #pragma unroll
        for (int ks = 0; ks < 4; ks++) {
            uint32_t af[4][4], bf[4][2];
            #pragma unroll
            for (int mt = 0; mt < 4; mt++)
                ldsm4(af[mt], As + ((wm * 64 + mt * 16 + arow) * KSTG
                                    + ks * 16 + akof) * 2);
            #pragma unroll
            for (int p = 0; p < 2; p++) {
                uint32_t b4[4];
                ldsm4(b4, Bs + ((wn * 32 + p * 16 + brow) * KSTG
                                + ks * 16 + bkof) * 2);
                bf[2 * p][0] = b4[0]; bf[2 * p][1] = b4[1];
                bf[2 * p + 1][0] = b4[2]; bf[2 * p + 1][1] = b4[3];
            }
            #pragma unroll
            for (int mt = 0; mt < 4; mt++)
                #pragma unroll
                for (int nt = 0; nt < 4; nt++)
                    mma16(acc[mt][nt], af[mt], bf[nt][0], bf[nt][1]);
        }
        __syncthreads();

        if (ch + 3 < nch) issue(ch + 3);
        else cp_commit();          // empty group keeps wait arithmetic exact
    }

    #pragma unroll
    for (int mt = 0; mt < 4; mt++) {
        const int r = m0 + wm * 64 + mt * 16 + gid;
        #pragma unroll
        for (int nt = 0; nt < 4; nt++) {
            const int col = n0 + wn * 32 + nt * 8 + tid4 * 2;
            if (HOUT) {
                __half* C = (__half*)Cv;
                *(__half2*)(C + (size_t)r * N + col) =
                    __floats2half2_rn(acc[mt][nt][0], acc[mt][nt][1]);
                *(__half2*)(C + (size_t)(r + 8) * N + col) =
                    __floats2half2_rn(acc[mt][nt][2], acc[mt][nt][3]);
            } else {
                float* C = (float*)Cv;
                float2 v0 = { acc[mt][nt][0], acc[mt][nt][1] };
                float2 v1 = { acc[mt][nt][2], acc[mt][nt][3] };
                *(float2*)(C + (size_t)r * N + col)       = v0;
                *(float2*)(C + (size_t)(r + 8) * N + col) = v1;
            }
        }
    }
}

// ---------------------------------------------------------------------------
// Small kernels
// ---------------------------------------------------------------------------
__global__ void convert_x(const float* __restrict__ X, __half* __restrict__ Xh,
                          int n4) {
    int idx = blockIdx.x * blockDim.x + threadIdx.x;
    if (idx >= n4) return;
    float4 v = ((const float4*)X)[idx];
    ((__half2*)Xh)[2 * idx]     = __floats2half2_rn(v.x, v.y);
    ((__half2*)Xh)[2 * idx + 1] = __floats2half2_rn(v.z, v.w);
}

__global__ void transpose_kh(const float* __restrict__ W, __half* __restrict__ Wt,
                             int R, int C) {
    __shared__ float tile[32][33];
    int c0 = blockIdx.x * 32, r0 = blockIdx.y * 32;
    int tx = threadIdx.x;
    for (int j = threadIdx.y; j < 32; j += 8)
        tile[j][tx] = W[(size_t)(r0 + j) * C + c0 + tx];
    __syncthreads();
    for (int j = threadIdx.y; j < 32; j += 8)
        Wt[(size_t)(c0 + j) * R + r0 + tx] = __float2half_rn(tile[tx][j]);
}

__global__ void rope_table(const int* __restrict__ pos) {
    int idx = blockIdx.x * blockDim.x + threadIdx.x;
    if (idx >= BSTOK * 32) return;
    int i = idx & 31, bs = idx >> 5;
    double inv_freq = exp(-(double)i * (9.210340371976184 / 32.0));
    double a = (double)pos[bs] * inv_freq;
    double s, c;
    sincos(a, &s, &c);
    g_cos[idx] = (float)c;
    g_sin[idx] = (float)s;
}

// Single launch covering Q (32 heads) then K (8 heads) regions of QKV.
#define ROPE_Q (BSTOK * NH * 32)
#define ROPE_T (BSTOK * (NH + NKV) * 32)
__global__ void rope_all(__half* __restrict__ X) {
    int idx = blockIdx.x * blockDim.x + threadIdx.x;
    if (idx >= ROPE_T) return;
    int nheads, off, lidx;
    if (idx < ROPE_Q) { nheads = NH;  off = 0;    lidx = idx; }
    else              { nheads = NKV; off = KOFF; lidx = idx - ROPE_Q; }
    int i  = lidx & 31;
    int h  = (lidx >> 5) % nheads;
    int bs = lidx / (nheads * 32);
    float c  = g_cos[bs * 32 + i];
    float sn = g_sin[bs * 32 + i];
    __half* p = X + (size_t)bs * QKVS + off + h * HD;
    float x1 = __half2float(p[i]), x2 = __half2float(p[i + 32]);
    p[i]      = __float2half_rn(x1 * c - x2 * sn);
    p[i + 32] = __float2half_rn(x2 * c + x1 * sn);
}

// ---------------------------------------------------------------------------
// fp16 flash attention: 64-query CTA (4 warps), cp.async double-buffered
// K/V tiles, GQA 4:1, causal. Heavy CTAs scheduled first (reversed qb).
// ---------------------------------------------------------------------------
#define KSTH 72
#define KVT (64 * KSTH)
#define FLASH_SMEM (5 * KVT * 2)   // 46080 B

__global__ __launch_bounds__(128, 1) void flash_h(
    const __half* __restrict__ QKV, __half* __restrict__ Oh) {
    extern __shared__ __half fsh[];
    const uint32_t fbase = smem_u32(fsh);
    __half* Ss = fsh + 4 * KVT;
    const uint32_t ssb = fbase + 4 * KVT * 2;

    const int tid  = threadIdx.x;
    const int warp = tid >> 5;
    const int lane = tid & 31;
    const int gid  = lane >> 2;
    const int tid4 = lane & 3;
    const int qb = gridDim.x - 1 - blockIdx.x;   // heavy CTAs first
    const int h = blockIdx.y, b = blockIdx.z;
    const int hkv = h >> 2;
    const int row0 = warp * 16;

    const int arow = (lane & 7) + ((lane >> 3) & 1) * 8;
    const int akof = (lane >> 4) * 8;
    const int brow = (lane & 7) + (lane >> 4) * 8;
    const int bkof = ((lane >> 3) & 1) * 8;
    const int vrow = (lane & 7) + ((lane >> 3) & 1) * 8;
    const int vkof = (lane >> 4) * 8;

    int klin[4], kv_[4];
    #pragma unroll
    for (int i = 0; i < 4; i++) {
        int lin = i * 128 + tid;
        klin[i] = lin >> 3;
        kv_[i]  = lin & 7;
    }
    auto issue = [&](int kt) {
        uint32_t Kb = fbase + (kt & 1) * 2 * KVT * 2;
        uint32_t Vb = Kb + KVT * 2;
        #pragma unroll
        for (int i = 0; i < 4; i++) {
            size_t rowb = (size_t)(b * SEQ + kt * 64 + klin[i]) * QKVS
                          + hkv * HD + kv_[i] * 8;
            uint32_t so = (uint32_t)(klin[i] * KSTH + kv_[i] * 8) * 2;
            cp16(Kb + so, QKV + rowb + KOFF);
            cp16(Vb + so, QKV + rowb + VOFF);
        }
        cp_commit();
    };

    #pragma unroll
    for (int j = 0; j < 4; j++) {
        int idx = j * 32 + lane;
        int r = idx >> 3, v = idx & 7;
        int token = b * SEQ + qb * 64 + row0 + r;
        *(uint4*)(Ss + (row0 + r) * KSTH + v * 8) =
            *(const uint4*)(QKV + (size_t)token * QKVS + h * HD + v * 8);
    }
    __syncwarp();
    uint32_t qf[4][4];
    #pragma unroll
    for (int ks = 0; ks < 4; ks++)
        ldsm4(qf[ks], ssb + ((row0 + arow) * KSTH + ks * 16 + akof) * 2);
    __syncwarp();

    float o[8][4];
    #pragma unroll
    for (int nt = 0; nt < 8; nt++)
        #pragma unroll
        for (int i = 0; i < 4; i++) o[nt][i] = 0.f;
    float m0 = -1e30f, m1 = -1e30f, l0 = 0.f, l1 = 0.f;

    issue(0);

    for (int kt = 0; kt <= qb; kt++) {
        if (kt < qb) { issue(kt + 1); asm volatile("cp.async.wait_group 1;"); }
        else         {                asm volatile("cp.async.wait_group 0;"); }
        __syncthreads();

        const uint32_t ksb = fbase + (kt & 1) * 2 * KVT * 2;
        const uint32_t vsb = ksb + KVT * 2;

        float c[8][4];
        #pragma unroll
        for (int nt = 0; nt < 8; nt++)
            #pragma unroll
            for (int i = 0; i < 4; i++) c[nt][i] = 0.f;
        #pragma unroll
        for (int ks = 0; ks < 4; ks++)
            #pragma unroll
            for (int p = 0; p < 4; p++) {
                uint32_t b4[4];
                ldsm4(b4, ksb + ((p * 16 + brow) * KSTH + ks * 16 + bkof) * 2);
                mma16(c[2 * p],     qf[ks], b4[0], b4[1]);
                mma16(c[2 * p + 1], qf[ks], b4[2], b4[3]);
            }

        #pragma unroll
        for (int nt = 0; nt < 8; nt++)
            #pragma unroll
            for (int i = 0; i < 4; i++) c[nt][i] *= 0.125f;
        if (kt == qb) {
            const int r0l = row0 + gid, r1l = row0 + gid + 8;
            #pragma unroll
            for (int nt = 0; nt < 8; nt++) {
                int cb = nt * 8 + 2 * tid4;
                if (cb     > r0l) c[nt][0] = -1e30f;
                if (cb + 1 > r0l) c[nt][1] = -1e30f;
                if (cb     > r1l) c[nt][2] = -1e30f;
                if (cb + 1 > r1l) c[nt][3] = -1e30f;
            }
        }

        float t0 = -1e30f, t1 = -1e30f;
        #pragma unroll
        for (int nt = 0; nt < 8; nt++) {
            t0 = fmaxf(t0, fmaxf(c[nt][0], c[nt][1]));
            t1 = fmaxf(t1, fmaxf(c[nt][2], c[nt][3]));
        }
        t0 = fmaxf(t0, __shfl_xor_sync(0xffffffffu, t0, 1));
        t0 = fmaxf(t0, __shfl_xor_sync(0xffffffffu, t0, 2));
        t1 = fmaxf(t1, __shfl_xor_sync(0xffffffffu, t1, 1));
        t1 = fmaxf(t1, __shfl_xor_sync(0xffffffffu, t1, 2));
        float m0n = fmaxf(m0, t0);
        float m1n = fmaxf(m1, t1);
        float cor0 = __expf(m0 - m0n);
        float cor1 = __expf(m1 - m1n);
        #pragma unroll
        for (int nt = 0; nt < 8; nt++) {
            o[nt][0] *= cor0; o[nt][1] *= cor0;
            o[nt][2] *= cor1; o[nt][3] *= cor1;
        }

        float s0 = 0.f, s1 = 0.f;
        #pragma unroll
        for (int nt = 0; nt < 8; nt++) {
            float p0 = __expf(c[nt][0] - m0n);
            float p1 = __expf(c[nt][1] - m0n);
            float p2 = __expf(c[nt][2] - m1n);
            float p3 = __expf(c[nt][3] - m1n);
            s0 += p0 + p1;
            s1 += p2 + p3;
            *(__half2*)(Ss + (row0 + gid)     * KSTH + nt * 8 + 2 * tid4) =
                __floats2half2_rn(p0, p1);
            *(__half2*)(Ss + (row0 + gid + 8) * KSTH + nt * 8 + 2 * tid4) =
                __floats2half2_rn(p2, p3);
        }
        s0 += __shfl_xor_sync(0xffffffffu, s0, 1);
        s0 += __shfl_xor_sync(0xffffffffu, s0, 2);
        s1 += __shfl_xor_sync(0xffffffffu, s1, 1);
        s1 += __shfl_xor_sync(0xffffffffu, s1, 2);
        l0 = l0 * cor0 + s0;
        l1 = l1 * cor1 + s1;
        m0 = m0n; m1 = m1n;
        __syncwarp();

        #pragma unroll
        for (int ks = 0; ks < 4; ks++) {
            uint32_t a4[4];
            ldsm4(a4, ssb + ((row0 + arow) * KSTH + ks * 16 + akof) * 2);
            #pragma unroll
            for (int p = 0; p < 4; p++) {
                uint32_t b4[4];
                ldsm4t(b4, vsb + ((ks * 16 + vrow) * KSTH + p * 16 + vkof) * 2);
                mma16(o[2 * p],     a4, b4[0], b4[1]);
                mma16(o[2 * p + 1], a4, b4[2], b4[3]);
            }
        }
        __syncthreads();
    }

    float inv0 = 1.f / l0, inv1 = 1.f / l1;
    int token0 = b * SEQ + qb * 64 + row0 + gid;
    __half* op0 = Oh + (size_t)token0 * HIDDEN + h * HD;
    __half* op1 = op0 + (size_t)8 * HIDDEN;
    #pragma unroll
    for (int nt = 0; nt < 8; nt++) {
        int col = nt * 8 + 2 * tid4;
        *(__half2*)(op0 + col) = __floats2half2_rn(o[nt][0] * inv0, o[nt][1] * inv0);
        *(__half2*)(op1 + col) = __floats2half2_rn(o[nt][2] * inv1, o[nt][3] * inv1);
    }
}

// ---------------------------------------------------------------------------
// Launch sequence (QKV GEMM is the 6th launch -> ncu capture target)
// ---------------------------------------------------------------------------
extern "C" void kernel_launch(void* const* d_in, const int* in_sizes, int n_in,
                              void* d_out, int out_size) {
    const float* x   = (const float*)d_in[0];
    const float* Wq  = (const float*)d_in[1];
    const float* Wk  = (const float*)d_in[2];
    const float* Wv  = (const float*)d_in[3];
    const float* Wo  = (const float*)d_in[4];
    const int*   pos = (const int*)d_in[5];
    float* out = (float*)d_out;

    __half *xh, *QKVh, *Oh, *Wqkv, *WtO;
    cudaGetSymbolAddress((void**)&xh,   g_xh);
    cudaGetSymbolAddress((void**)&QKVh, g_QKVh);
    cudaGetSymbolAddress((void**)&Oh,   g_Oh);
    cudaGetSymbolAddress((void**)&Wqkv, g_Wqkv);
    cudaGetSymbolAddress((void**)&WtO,  g_WtO);

    cudaFuncSetAttribute(gemm_h<true>,  cudaFuncAttributeMaxDynamicSharedMemorySize, GEMM_SMEM_BYTES);
    cudaFuncSetAttribute(gemm_h<false>, cudaFuncAttributeMaxDynamicSharedMemorySize, GEMM_SMEM_BYTES);
    cudaFuncSetAttribute(flash_h,       cudaFuncAttributeMaxDynamicSharedMemorySize, FLASH_SMEM);

    const int M = BSTOK;        // 4096
    dim3 tb(32, 8);

    // 1: convert x
    convert_x<<<(BSTOK * HIDDEN / 4 + 255) / 256, 256>>>(x, xh, BSTOK * HIDDEN / 4);
    // 2-4: QKV weight transposes
    transpose_kh<<<dim3(HIDDEN / 32, HIDDEN / 32), tb>>>(Wq, Wqkv, HIDDEN, HIDDEN);
    transpose_kh<<<dim3((NKV * HD) / 32, HIDDEN / 32), tb>>>(
        Wk, Wqkv + (size_t)KOFF * HIDDEN, HIDDEN, NKV * HD);
    transpose_kh<<<dim3((NKV * HD) / 32, HIDDEN / 32), tb>>>(
        Wv, Wqkv + (size_t)VOFF * HIDDEN, HIDDEN, NKV * HD);
    // 5: rope table (independent)
    rope_table<<<(BSTOK * 32 + 255) / 256, 256>>>(pos);

    // 6: fused QKV projection
    gemm_h<true><<<dim3(QKVS / 128, M / 128), 256, GEMM_SMEM_BYTES>>>(
        xh, Wqkv, QKVh, M, QKVS, HIDDEN);

    // 7: rope (Q + K in one launch)
    rope_all<<<(ROPE_T + 255) / 256, 256>>>(QKVh);

    // 8: flash attention
    flash_h<<<dim3(SEQ / 64, NH, BB), 128, FLASH_SMEM>>>(QKVh, Oh);

    // 9: Wo transpose, 10: output projection
    transpose_kh<<<dim3(HIDDEN / 32, HIDDEN / 32), tb>>>(Wo, WtO, HIDDEN, HIDDEN);
    gemm_h<false><<<dim3(HIDDEN / 128, M / 128), 256, GEMM_SMEM_BYTES>>>(
        Oh, WtO, out, M, HIDDEN, HIDDEN);
}